// round 14
// baseline (speedup 1.0000x reference)
#include <cuda_runtime.h>
#include <cstdint>

#define T_STEPS 1000
#define BATCH   64
#define NIN     512
#define NOUT    128
#define LRATE   1.0e-3f
#define DECAY   0.9f

#define NCTA 128
#define NTHR 256
#define FSTRIDE 32   // u32 stride between epoch-record words (128B)

// ------------- tagged cross-CTA exchange buffers (double-buffered) -----
// packet = (epoch in low 32, f32 bits in high 32) written as one 8B atom
__device__ __align__(16) unsigned long long g_zp[2][16 * 64 * 8 * 8]; // [par][((oc*64+b)*8+ic)*8+o]
__device__ __align__(16) unsigned long long g_Et[2][NOUT * BATCH];    // [par][o*64+b]
__device__ __align__(16) unsigned long long g_pt[2][BATCH * 16];      // [par][b*16+oc]
__device__ __align__(128) unsigned g_ep[NCTA * FSTRIDE];              // per-CTA epoch record

// ---------------- packed f32x2 helpers --------------------------------
__device__ __forceinline__ unsigned long long pack2(float lo, float hi) {
    unsigned long long r;
    asm("mov.b64 %0, {%1, %2};" : "=l"(r) : "f"(lo), "f"(hi));
    return r;
}
__device__ __forceinline__ unsigned long long ffma2(unsigned long long a,
                                                    unsigned long long b,
                                                    unsigned long long c) {
    unsigned long long d;
    asm("fma.rn.f32x2 %0, %1, %2, %3;" : "=l"(d) : "l"(a), "l"(b), "l"(c));
    return d;
}
__device__ __forceinline__ unsigned long long addf2(unsigned long long a,
                                                    unsigned long long b) {
    unsigned long long d;
    asm("add.rn.f32x2 %0, %1, %2;" : "=l"(d) : "l"(a), "l"(b));
    return d;
}
__device__ __forceinline__ void unpack2(unsigned long long v, float& lo, float& hi) {
    asm("mov.b64 {%0, %1}, %2;" : "=f"(lo), "=f"(hi) : "l"(v));
}

// ---------------- tagged-packet helpers --------------------------------
__device__ __forceinline__ unsigned long long tag_pack(float f, unsigned e) {
    return ((unsigned long long)__float_as_uint(f) << 32) | (unsigned long long)e;
}
__device__ __forceinline__ float tag_val(unsigned long long v) {
    return __uint_as_float((unsigned)(v >> 32));
}
__device__ __forceinline__ int tag_ok(unsigned long long v, unsigned e) {
    return (int)((unsigned)v - e) >= 0;
}
__device__ __forceinline__ unsigned long long ld_rlx64(const unsigned long long* p) {
    unsigned long long v;
    asm volatile("ld.relaxed.gpu.u64 %0, [%1];" : "=l"(v) : "l"(p) : "memory");
    return v;
}
__device__ __forceinline__ void st_rlx64(unsigned long long* p, unsigned long long v) {
    asm volatile("st.relaxed.gpu.u64 [%0], %1;" :: "l"(p), "l"(v) : "memory");
}

#define COMP(v,k) ((k)==0 ? (v).x : (k)==1 ? (v).y : (k)==2 ? (v).z : (v).w)

__global__ void __launch_bounds__(NTHR, 1)
bstdp_kernel(const float* __restrict__ spikes,
             const float* __restrict__ weight,
             const float* __restrict__ bias_in,
             float* __restrict__ out,
             int write_u)
{
    // persistent CTA-local state
    __shared__ __align__(16) float psp_s[64 * 68];   // [b][i-slice 64], padded
    __shared__ __align__(16) float Wp_s[8 * 76];     // [o-local][i-local 64], padded
    __shared__ __align__(16) float EWp_s[8 * 76];    // exp(-W) patch
    __shared__ __align__(16) float zo_s[8 * 64];     // [j][b]
    __shared__ float rden_s[64];
    __shared__ float pm_s[8];
    __shared__ float bias_s[8];
    __shared__ float u_sm[64];                       // [b-local 8][o-local 8]
    __shared__ unsigned e0_sm;                       // epoch base, ALL threads

    const int tid  = threadIdx.x;
    const int cta  = blockIdx.x;
    const int w_id = tid >> 5;
    const int lane = tid & 31;
    const int oc   = cta >> 3;     // 0..15
    const int ic   = cta & 7;      // 0..7 (doubles as bc in phase B)

    // quiescent epoch base from own record (equal across CTAs at launch)
    if (tid == 0) {
        unsigned e0;
        asm volatile("ld.relaxed.gpu.u32 %0, [%1];"
                     : "=r"(e0) : "l"(g_ep + cta * FSTRIDE) : "memory");
        e0_sm = e0;
    }

    // ---------------- init: W/EW patch, bias, u, psp tile ----------------
    if (tid < 128) {
        int ol = tid >> 4, il4 = tid & 15;
        float4 w = *(const float4*)(weight + (oc * 8 + ol) * NIN + ic * 64 + il4 * 4);
        *(float4*)(Wp_s + ol * 76 + il4 * 4) = w;
        float4 e;
        e.x = __expf(-w.x); e.y = __expf(-w.y);
        e.z = __expf(-w.z); e.w = __expf(-w.w);
        *(float4*)(EWp_s + ol * 76 + il4 * 4) = e;
    }
    if (tid < 8)  bias_s[tid] = bias_in[oc * 8 + tid];
    if (tid < 64) u_sm[tid] = 0.0f;
    {
        const float4* sp0 = (const float4*)spikes;
#pragma unroll
        for (int rr = 0; rr < 4; rr++) {
            int idx = tid + rr * 256;
            int b = idx >> 4, i4 = idx & 15;
            *(float4*)(psp_s + b * 68 + i4 * 4) = sp0[b * 128 + ic * 16 + i4];
        }
    }
    __syncthreads();
    const unsigned E0 = e0_sm;

    // phase-A thread map: 16 bblk(4 b) x 16 ks(4 k)
    const int bblk = tid >> 4;
    const int ksA  = tid & 15;
    // phase-C GEMM2 map: 32 blocks x 8 ks over b
    const int blkC = tid >> 3;
    const int ksC  = tid & 7;
    const int jbC  = blkC >> 4;    // 0..1
    const int ibC  = blkC & 15;    // 0..15

    float4 spk[4];                 // spikes(t+1), loaded in phase B

    // ---------------- phase A: local GEMM1 partial → tagged zpart ---------
    auto phaseA = [&](int t) {
        const unsigned e = E0 + (unsigned)t + 1u;
        const int par = t & 1;
        float4 pv[4], wv[8];
#pragma unroll
        for (int r = 0; r < 4; r++)
            pv[r] = *(const float4*)(psp_s + (bblk * 4 + r) * 68 + ksA * 4);
#pragma unroll
        for (int o = 0; o < 8; o++)
            wv[o] = *(const float4*)(Wp_s + o * 76 + ksA * 4);

        unsigned long long acc2[16];
#pragma unroll
        for (int i = 0; i < 16; i++) acc2[i] = 0ull;
#pragma unroll
        for (int k = 0; k < 4; k++) {
            unsigned long long pp[4], ww[4];
#pragma unroll
            for (int r = 0; r < 4; r++) {
                float c = COMP(pv[r], k);
                pp[r] = pack2(c, c);
            }
#pragma unroll
            for (int op = 0; op < 4; op++)
                ww[op] = pack2(COMP(wv[2 * op], k), COMP(wv[2 * op + 1], k));
#pragma unroll
            for (int r = 0; r < 4; r++)
#pragma unroll
                for (int op = 0; op < 4; op++)
                    acc2[r * 4 + op] = ffma2(pp[r], ww[op], acc2[r * 4 + op]);
        }
        // 16-way value-splitting reduction over ksA
#pragma unroll
        for (int i = 0; i < 8; i++) {
            bool hi = ksA & 1;
            unsigned long long send = hi ? acc2[i] : acc2[i + 8];
            unsigned long long keep = hi ? acc2[i + 8] : acc2[i];
            acc2[i] = addf2(keep, __shfl_xor_sync(0xffffffffu, send, 1));
        }
#pragma unroll
        for (int i = 0; i < 4; i++) {
            bool hi = ksA & 2;
            unsigned long long send = hi ? acc2[i] : acc2[i + 4];
            unsigned long long keep = hi ? acc2[i + 4] : acc2[i];
            acc2[i] = addf2(keep, __shfl_xor_sync(0xffffffffu, send, 2));
        }
#pragma unroll
        for (int i = 0; i < 2; i++) {
            bool hi = ksA & 4;
            unsigned long long send = hi ? acc2[i] : acc2[i + 2];
            unsigned long long keep = hi ? acc2[i + 2] : acc2[i];
            acc2[i] = addf2(keep, __shfl_xor_sync(0xffffffffu, send, 4));
        }
        {
            bool hi = ksA & 8;
            unsigned long long send = hi ? acc2[0] : acc2[1];
            unsigned long long keep = hi ? acc2[1] : acc2[0];
            acc2[0] = addf2(keep, __shfl_xor_sync(0xffffffffu, send, 8));
        }
        int basev = ((ksA & 1) ? 8 : 0) | ((ksA & 2) ? 4 : 0) |
                    ((ksA & 4) ? 2 : 0) | ((ksA & 8) ? 1 : 0);
        int r = basev >> 2, op = basev & 3;
        int b = bblk * 4 + r;
        float2 z2;
        unpack2(acc2[0], z2.x, z2.y);
        unsigned long long* dst = g_zp[par] + ((oc * 64 + b) * 8 + ic) * 8 + 2 * op;
        st_rlx64(dst,     tag_pack(z2.x, e));
        st_rlx64(dst + 1, tag_pack(z2.y, e));
    };

    // ---------------- phase B: poll zpart, u, exp → tagged E/part ---------
    auto phaseB = [&](int t) {
        const unsigned e = E0 + (unsigned)t + 1u;
        const int par = t & 1;
        // prefetch spikes(t+1) for phase C's psp advance
        if (t + 1 < T_STEPS) {
            const float4* sp = (const float4*)(spikes + (size_t)(t + 1) * (BATCH * NIN));
#pragma unroll
            for (int rr = 0; rr < 4; rr++) {
                int idx = tid + rr * 256;
                int b = idx >> 4, i4 = idx & 15;
                spk[rr] = sp[b * 128 + ic * 16 + i4];
            }
        }
        if (tid < 64) {
            int bl = tid >> 3, ol = tid & 7;
            int b = ic * 8 + bl;
            const unsigned long long* zp = g_zp[par] + (oc * 64 + b) * 64 + ol;
            unsigned long long v[8];
#pragma unroll
            for (int icp = 0; icp < 8; icp++) v[icp] = ld_rlx64(zp + icp * 8);
#pragma unroll
            for (int icp = 0; icp < 8; icp++)
                while (!tag_ok(v[icp], e)) v[icp] = ld_rlx64(zp + icp * 8);
            float z = ((tag_val(v[0]) + tag_val(v[1])) + (tag_val(v[2]) + tag_val(v[3])))
                    + ((tag_val(v[4]) + tag_val(v[5])) + (tag_val(v[6]) + tag_val(v[7])))
                    + bias_s[ol];
            float u = DECAY * u_sm[tid] + z;
            u_sm[tid] = u;
            float ev = __expf(u);       // shift-free softmax numerator
            st_rlx64(&g_Et[par][(oc * 8 + ol) * 64 + b], tag_pack(ev, e));
            float es = ev;
            es += __shfl_xor_sync(0xffffffffu, es, 1);
            es += __shfl_xor_sync(0xffffffffu, es, 2);
            es += __shfl_xor_sync(0xffffffffu, es, 4);
            if (ol == 0) st_rlx64(&g_pt[par][b * 16 + oc], tag_pack(es, e));
        }
    };

    // ---------------- phase C: poll part/E, z_out, GEMM2, updates ---------
    auto phaseC = [&](int t) {
        const unsigned e = E0 + (unsigned)t + 1u;
        const int par = t & 1;
        // issue E packet loads early (overlap with part poll)
        unsigned long long evt[4];
        const unsigned long long* ebase = g_Et[par] + oc * 512 + tid * 4;
        if (tid < 128) {
#pragma unroll
            for (int k = 0; k < 4; k++) evt[k] = ld_rlx64(ebase + k);
        }
        // softmax denominators: poll 16 tagged partials per b
        if (tid < 64) {
            const unsigned long long* pbase = g_pt[par] + tid * 16;
            unsigned long long pv[16];
#pragma unroll
            for (int k = 0; k < 16; k++) pv[k] = ld_rlx64(pbase + k);
#pragma unroll
            for (int k = 0; k < 16; k++)
                while (!tag_ok(pv[k], e)) pv[k] = ld_rlx64(pbase + k);
            float s = (((tag_val(pv[0])  + tag_val(pv[1]))  + (tag_val(pv[2])  + tag_val(pv[3])))
                    +  ((tag_val(pv[4])  + tag_val(pv[5]))  + (tag_val(pv[6])  + tag_val(pv[7]))))
                    + (((tag_val(pv[8])  + tag_val(pv[9]))  + (tag_val(pv[10]) + tag_val(pv[11])))
                    +  ((tag_val(pv[12]) + tag_val(pv[13])) + (tag_val(pv[14]) + tag_val(pv[15]))));
            rden_s[tid] = 1.0f / s;
        }
        if (tid < 128) {
#pragma unroll
            for (int k = 0; k < 4; k++)
                while (!tag_ok(evt[k], e)) evt[k] = ld_rlx64(ebase + k);
        }
        __syncthreads();
        if (tid < 128) {
            int h = tid * 4;
            int j = h >> 6, b = h & 63;
            float4 rv = *(const float4*)(rden_s + b);
            float4 zv;
            zv.x = tag_val(evt[0]) * rv.x; zv.y = tag_val(evt[1]) * rv.y;
            zv.z = tag_val(evt[2]) * rv.z; zv.w = tag_val(evt[3]) * rv.w;
            *(float4*)(zo_s + j * 64 + b) = zv;
        }
        __syncthreads();
        // post_mean: one warp per output row
        {
            float s = zo_s[w_id * 64 + lane] + zo_s[w_id * 64 + 32 + lane];
#pragma unroll
            for (int m = 16; m > 0; m >>= 1)
                s += __shfl_xor_sync(0xffffffffu, s, m);
            if (lane == 0) pm_s[w_id] = s * (1.0f / BATCH);
        }
        // emit z_out_stack[t]
        if (tid < 64) {
            int b = ic * 8 + (tid >> 3), j = tid & 7;
            out[(size_t)t * (BATCH * NOUT) + b * NOUT + oc * 8 + j] =
                zo_s[j * 64 + b];
        }

        // GEMM2: pp[j][i] = sum_b zo[j][b] * psp[b][i]
        unsigned long long acc2[8];
#pragma unroll
        for (int i = 0; i < 8; i++) acc2[i] = 0ull;
#pragma unroll
        for (int m = 0; m < 8; m++) {
            int b = ksC + (m << 3);
            ulonglong2 pv = *(const ulonglong2*)(psp_s + b * 68 + (ibC << 2));
#pragma unroll
            for (int jj = 0; jj < 4; jj++) {
                float z = zo_s[(jbC * 4 + jj) * 64 + b];
                unsigned long long zz = pack2(z, z);
                acc2[jj * 2 + 0] = ffma2(zz, pv.x, acc2[jj * 2 + 0]);
                acc2[jj * 2 + 1] = ffma2(zz, pv.y, acc2[jj * 2 + 1]);
            }
        }
#pragma unroll
        for (int i = 0; i < 4; i++) {
            bool hi = ksC & 1;
            unsigned long long send = hi ? acc2[i] : acc2[i + 4];
            unsigned long long keep = hi ? acc2[i + 4] : acc2[i];
            acc2[i] = addf2(keep, __shfl_xor_sync(0xffffffffu, send, 1));
        }
#pragma unroll
        for (int i = 0; i < 2; i++) {
            bool hi = ksC & 2;
            unsigned long long send = hi ? acc2[i] : acc2[i + 2];
            unsigned long long keep = hi ? acc2[i + 2] : acc2[i];
            acc2[i] = addf2(keep, __shfl_xor_sync(0xffffffffu, send, 2));
        }
        {
            bool hi = ksC & 4;
            unsigned long long send = hi ? acc2[0] : acc2[1];
            unsigned long long keep = hi ? acc2[1] : acc2[0];
            acc2[0] = addf2(keep, __shfl_xor_sync(0xffffffffu, send, 4));
        }
        __syncthreads();   // pm_s ready; GEMM2 psp reads complete

        // W/EW update: every thread owns 2 consecutive W elements
        {
            int basev = ((ksC & 1) ? 4 : 0) | ((ksC & 2) ? 2 : 0) | ((ksC & 4) ? 1 : 0);
            int jj = basev >> 1, ip = basev & 1;
            int o_l = jbC * 4 + jj;
            int i_l = (ibC << 2) + 2 * ip;
            float2 ppv;
            unpack2(acc2[0], ppv.x, ppv.y);
            float2* wp  = (float2*)(Wp_s + o_l * 76 + i_l);
            float2* ewp = (float2*)(EWp_s + o_l * 76 + i_l);
            float2 w  = *wp;
            float2 ew = *ewp;
            float pmv = pm_s[o_l];
            float d0 = LRATE * (ew.x * (ppv.x * (1.0f / BATCH)) - pmv);
            float d1 = LRATE * (ew.y * (ppv.y * (1.0f / BATCH)) - pmv);
            w.x += d0; w.y += d1;
            ew.x *= (1.0f - d0 + 0.5f * d0 * d0);
            ew.y *= (1.0f - d1 + 0.5f * d1 * d1);
            *wp = w;
            *ewp = ew;
        }
        if (tid < 8) {
            float bb = bias_s[tid];
            bias_s[tid] = bb + LRATE * (__expf(-bb) - 1.0f) * pm_s[tid];
        }
        // psp advance (spikes prefetched in phase B)
        if (t + 1 < T_STEPS) {
#pragma unroll
            for (int rr = 0; rr < 4; rr++) {
                int idx = tid + rr * 256;
                int b = idx >> 4, i4 = idx & 15;
                float4* pp = (float4*)(psp_s + b * 68 + i4 * 4);
                float4 pv = *pp;
                pv.x = DECAY * pv.x + spk[rr].x;
                pv.y = DECAY * pv.y + spk[rr].y;
                pv.z = DECAY * pv.z + spk[rr].z;
                pv.w = DECAY * pv.w + spk[rr].w;
                *pp = pv;
            }
        }
        __syncthreads();   // W/psp stable before next phase A
    };

    // ================= barrier-free main loop =============================
    phaseA(0);
    phaseB(0);
    for (int t = 0; t < T_STEPS; ++t) {
        phaseC(t);
        if (t + 1 < T_STEPS) {
            phaseA(t + 1);
            phaseB(t + 1);
        }
    }

    // epoch record for next launch (graph replay): all CTAs store same value
    if (tid == 0)
        asm volatile("st.relaxed.gpu.u32 [%0], %1;"
                     :: "l"(g_ep + cta * FSTRIDE), "r"(E0 + (unsigned)T_STEPS) : "memory");

    // ---------------- final membrane potential u_final --------------------
    if (write_u && tid < 64) {
        int b = ic * 8 + (tid >> 3);
        int o = oc * 8 + (tid & 7);
        out[(size_t)T_STEPS * BATCH * NOUT + b * NOUT + o] = u_sm[tid];
    }
}

extern "C" void kernel_launch(void* const* d_in, const int* in_sizes, int n_in,
                              void* d_out, int out_size) {
    const float* spikes = nullptr;
    const float* weight = nullptr;
    const float* bias   = nullptr;
    for (int i = 0; i < n_in; i++) {
        if (in_sizes[i] == T_STEPS * BATCH * NIN)      spikes = (const float*)d_in[i];
        else if (in_sizes[i] == NOUT * NIN)            weight = (const float*)d_in[i];
        else if (in_sizes[i] == NOUT)                  bias   = (const float*)d_in[i];
    }
    int write_u = (out_size >= T_STEPS * BATCH * NOUT + BATCH * NOUT) ? 1 : 0;
    bstdp_kernel<<<NCTA, NTHR>>>(spikes, weight, bias, (float*)d_out, write_u);
}

// round 15
// speedup vs baseline: 3.2543x; 3.2543x over previous
#include <cuda_runtime.h>
#include <cstdint>

#define T_STEPS 1000
#define BATCH   64
#define NIN     512
#define NOUT    128
#define LRATE   1.0e-3f
#define DECAY   0.9f

#define NCTA 128
#define NTHR 256
#define FSTRIDE 32   // u32 stride between flag words (128B: one L2 line each)

// ---------------- global scratch --------------------------------------
__device__ __align__(16) float g_zpart[16 * BATCH * 8 * 8]; // [oc][b][ic][o8]
__device__ __align__(16) float g_E[NOUT * BATCH];           // exp(u), [o][b]
__device__ __align__(16) float g_part[2][BATCH * 16];       // [par][b][oc]
__device__ __align__(128) unsigned g_fA[NCTA * FSTRIDE];    // group-sync flags
__device__ __align__(128) unsigned g_fB[NCTA * FSTRIDE];    // global-sync flags

// ---------------- packed f32x2 helpers --------------------------------
__device__ __forceinline__ unsigned long long pack2(float lo, float hi) {
    unsigned long long r;
    asm("mov.b64 %0, {%1, %2};" : "=l"(r) : "f"(lo), "f"(hi));
    return r;
}
__device__ __forceinline__ unsigned long long ffma2(unsigned long long a,
                                                    unsigned long long b,
                                                    unsigned long long c) {
    unsigned long long d;
    asm("fma.rn.f32x2 %0, %1, %2, %3;" : "=l"(d) : "l"(a), "l"(b), "l"(c));
    return d;
}
__device__ __forceinline__ unsigned long long addf2(unsigned long long a,
                                                    unsigned long long b) {
    unsigned long long d;
    asm("add.rn.f32x2 %0, %1, %2;" : "=l"(d) : "l"(a), "l"(b));
    return d;
}
__device__ __forceinline__ void unpack2(unsigned long long v, float& lo, float& hi) {
    asm("mov.b64 {%0, %1}, %2;" : "=f"(lo), "=f"(hi) : "l"(v));
}

__device__ __forceinline__ void st_rel(unsigned* p, unsigned v) {
    asm volatile("st.release.gpu.u32 [%0], %1;" :: "l"(p), "r"(v) : "memory");
}
__device__ __forceinline__ void poll_ge(const unsigned* p, unsigned tgt) {
    unsigned v;
    do {
        asm volatile("ld.acquire.gpu.u32 %0, [%1];" : "=r"(v) : "l"(p) : "memory");
    } while ((int)(v - tgt) < 0);
}

#define COMP(v,k) ((k)==0 ? (v).x : (k)==1 ? (v).y : (k)==2 ? (v).z : (v).w)

__global__ void __launch_bounds__(NTHR, 1)
bstdp_kernel(const float* __restrict__ spikes,
             const float* __restrict__ weight,
             const float* __restrict__ bias_in,
             float* __restrict__ out,
             int write_u)
{
    // persistent CTA-local state (psp double-buffered by step parity)
    __shared__ __align__(16) float psp_s[2][64 * 68]; // [par][b][i-slice], padded
    __shared__ __align__(16) float Wp_s[8 * 76];      // [o-local][i-local 64], padded
    __shared__ __align__(16) float EWp_s[8 * 76];     // exp(-W) patch
    __shared__ __align__(16) float zo_s[8 * 64];      // [j][b]
    __shared__ float rden_s[64];
    __shared__ float pm_s[8];
    __shared__ float bias_s[8];
    __shared__ float u_sm[64];                        // [b-local 8][o-local 8]
    __shared__ unsigned e0_sm;                        // epoch base, ALL threads

    const int tid  = threadIdx.x;
    const int cta  = blockIdx.x;
    const int w_id = tid >> 5;
    const int lane = tid & 31;
    const int oc   = cta >> 3;     // 0..15
    const int ic   = cta & 7;      // 0..7 (doubles as bc in phase B)

    // quiescent epoch base: all flags hold the same monotonic value between
    // launches (every CTA stores E0+T before exiting), so this is replay-safe.
    if (tid == 0) {
        unsigned e0;
        asm volatile("ld.relaxed.gpu.u32 %0, [%1];"
                     : "=r"(e0) : "l"(g_fB + cta * FSTRIDE) : "memory");
        e0_sm = e0;
    }

    // ---------------- init: W/EW patch, bias, u, psp tile ----------------
    if (tid < 128) {
        int ol = tid >> 4, il4 = tid & 15;
        float4 w = *(const float4*)(weight + (oc * 8 + ol) * NIN + ic * 64 + il4 * 4);
        *(float4*)(Wp_s + ol * 76 + il4 * 4) = w;
        float4 e;
        e.x = __expf(-w.x); e.y = __expf(-w.y);
        e.z = __expf(-w.z); e.w = __expf(-w.w);
        *(float4*)(EWp_s + ol * 76 + il4 * 4) = e;
    }
    if (tid < 8)  bias_s[tid] = bias_in[oc * 8 + tid];
    if (tid < 64) u_sm[tid] = 0.0f;
    {
        const float4* sp0 = (const float4*)spikes;
#pragma unroll
        for (int rr = 0; rr < 4; rr++) {
            int idx = tid + rr * 256;
            int b = idx >> 4, i4 = idx & 15;
            *(float4*)(psp_s[0] + b * 68 + i4 * 4) = sp0[b * 128 + ic * 16 + i4];
        }
    }
    __syncthreads();
    const unsigned E0 = e0_sm;

    // phase-A thread map: 16 bblk(4 b) x 16 ks(4 k)
    const int bblk = tid >> 4;
    const int ksA  = tid & 15;
    // phase-C GEMM2 map: 32 blocks x 8 ks over b
    const int blkC = tid >> 3;
    const int ksC  = tid & 7;
    const int jbC  = blkC >> 4;    // 0..1
    const int ibC  = blkC & 15;    // 0..15

    float4 spk[8];   // spikes(t+1): upper 128 threads only, 8 float4 each
    float4 ev;       // E packet, loaded under the global spin (tid<128)

    // ---------------- phase A: local GEMM1 partial ------------------------
    auto phaseA = [&](int t) {
        const float* P = psp_s[t & 1];
        float4 pv[4], wv[8];
#pragma unroll
        for (int r = 0; r < 4; r++)
            pv[r] = *(const float4*)(P + (bblk * 4 + r) * 68 + ksA * 4);
#pragma unroll
        for (int o = 0; o < 8; o++)
            wv[o] = *(const float4*)(Wp_s + o * 76 + ksA * 4);

        unsigned long long acc2[16];
#pragma unroll
        for (int i = 0; i < 16; i++) acc2[i] = 0ull;
#pragma unroll
        for (int k = 0; k < 4; k++) {
            unsigned long long pp[4], ww[4];
#pragma unroll
            for (int r = 0; r < 4; r++) {
                float c = COMP(pv[r], k);
                pp[r] = pack2(c, c);
            }
#pragma unroll
            for (int op = 0; op < 4; op++)
                ww[op] = pack2(COMP(wv[2 * op], k), COMP(wv[2 * op + 1], k));
#pragma unroll
            for (int r = 0; r < 4; r++)
#pragma unroll
                for (int op = 0; op < 4; op++)
                    acc2[r * 4 + op] = ffma2(pp[r], ww[op], acc2[r * 4 + op]);
        }
        // 16-way value-splitting reduction over ksA
#pragma unroll
        for (int i = 0; i < 8; i++) {
            bool hi = ksA & 1;
            unsigned long long send = hi ? acc2[i] : acc2[i + 8];
            unsigned long long keep = hi ? acc2[i + 8] : acc2[i];
            acc2[i] = addf2(keep, __shfl_xor_sync(0xffffffffu, send, 1));
        }
#pragma unroll
        for (int i = 0; i < 4; i++) {
            bool hi = ksA & 2;
            unsigned long long send = hi ? acc2[i] : acc2[i + 4];
            unsigned long long keep = hi ? acc2[i + 4] : acc2[i];
            acc2[i] = addf2(keep, __shfl_xor_sync(0xffffffffu, send, 2));
        }
#pragma unroll
        for (int i = 0; i < 2; i++) {
            bool hi = ksA & 4;
            unsigned long long send = hi ? acc2[i] : acc2[i + 2];
            unsigned long long keep = hi ? acc2[i + 2] : acc2[i];
            acc2[i] = addf2(keep, __shfl_xor_sync(0xffffffffu, send, 4));
        }
        {
            bool hi = ksA & 8;
            unsigned long long send = hi ? acc2[0] : acc2[1];
            unsigned long long keep = hi ? acc2[1] : acc2[0];
            acc2[0] = addf2(keep, __shfl_xor_sync(0xffffffffu, send, 8));
        }
        int basev = ((ksA & 1) ? 8 : 0) | ((ksA & 2) ? 4 : 0) |
                    ((ksA & 4) ? 2 : 0) | ((ksA & 8) ? 1 : 0);
        int r = basev >> 2, op = basev & 3;
        int b = bblk * 4 + r;
        float2 z2;
        unpack2(acc2[0], z2.x, z2.y);
        ((float2*)g_zpart)[((oc * 64 + b) * 8 + ic) * 4 + op] = z2;
    };

    // ------- group sync: flag store + 8-lane parallel poll (no atomics) ---
    auto syncA = [&](int t) {
        unsigned e = E0 + (unsigned)t + 1u;
        __syncthreads();
        if (tid == 0) st_rel(g_fA + cta * FSTRIDE, e);
        if (tid < 8)  poll_ge(g_fA + (oc * 8 + tid) * FSTRIDE, e);
        __syncthreads();
    };

    // ---------------- phase B: reduce partials, u, exp --------------------
    auto phaseB = [&](int t) {
        // prefetch spikes(t+1): upper 128 threads, full tile (8 float4 each)
        if (tid >= 128 && t + 1 < T_STEPS) {
            const float4* sp = (const float4*)(spikes + (size_t)(t + 1) * (BATCH * NIN));
#pragma unroll
            for (int rr = 0; rr < 8; rr++) {
                int idx = (tid - 128) + rr * 128;   // 0..1023
                int b = idx >> 4, i4 = idx & 15;
                spk[rr] = sp[b * 128 + ic * 16 + i4];
            }
        }
        if (tid < 64) {
            int bl = tid >> 3, ol = tid & 7;
            const float* zp = g_zpart + (oc * 64 + ic * 8 + bl) * 64 + ol;
            float s0 = zp[0]  + zp[8];
            float s1 = zp[16] + zp[24];
            float s2 = zp[32] + zp[40];
            float s3 = zp[48] + zp[56];
            float z = ((s0 + s1) + (s2 + s3)) + bias_s[ol];
            float u = DECAY * u_sm[tid] + z;
            u_sm[tid] = u;
            float e = __expf(u);       // shift-free softmax numerator
            g_E[(oc * 8 + ol) * 64 + ic * 8 + bl] = e;
            float es = e;
            es += __shfl_xor_sync(0xffffffffu, es, 1);
            es += __shfl_xor_sync(0xffffffffu, es, 2);
            es += __shfl_xor_sync(0xffffffffu, es, 4);
            if (ol == 0) g_part[t & 1][(ic * 8 + bl) * 16 + oc] = es;
        }
    };

    // ------ global barrier: flag store + overlapped spin ------------------
    auto arriveB = [&](int t) {
        __syncthreads();
        if (tid == 0) st_rel(g_fB + cta * FSTRIDE, E0 + (unsigned)t + 1u);
    };
    auto spinB = [&](int t) {
        unsigned e = E0 + (unsigned)t + 1u;
        if (tid < 128) {
            // 1) wait for the one group CTA producing our E float4
            int prod = oc * 8 + ((tid & 15) >> 1);
            poll_ge(g_fB + prod * FSTRIDE, e);
            // 2) issue E load (latency hides under the global poll)
            ev = ((const float4*)(g_E + oc * 512))[tid];
            // 3) global barrier: one flag per thread
            poll_ge(g_fB + tid * FSTRIDE, e);
        } else if (t + 1 < T_STEPS) {
            // upper threads: advance psp into the other parity meanwhile
            const float* Po = psp_s[t & 1];
            float* Pn = psp_s[(t + 1) & 1];
#pragma unroll
            for (int rr = 0; rr < 8; rr++) {
                int idx = (tid - 128) + rr * 128;
                int b = idx >> 4, i4 = idx & 15;
                float4 pv = *(const float4*)(Po + b * 68 + i4 * 4);
                pv.x = DECAY * pv.x + spk[rr].x;
                pv.y = DECAY * pv.y + spk[rr].y;
                pv.z = DECAY * pv.z + spk[rr].z;
                pv.w = DECAY * pv.w + spk[rr].w;
                *(float4*)(Pn + b * 68 + i4 * 4) = pv;
            }
        }
        __syncthreads();
    };

    // ---------------- phase C: z_out, GEMM2, updates ----------------------
    auto phaseC = [&](int t) {
        const float* P = psp_s[t & 1];
        // softmax denominators: one thread per b, 4x LDG.128 + local sum
        if (tid < 64) {
            const float4* pv = (const float4*)(g_part[t & 1] + tid * 16);
            float4 a = pv[0], b4 = pv[1], c4 = pv[2], d4 = pv[3];
            float s = (((a.x + a.y) + (a.z + a.w)) + ((b4.x + b4.y) + (b4.z + b4.w)))
                    + (((c4.x + c4.y) + (c4.z + c4.w)) + ((d4.x + d4.y) + (d4.z + d4.w)));
            rden_s[tid] = 1.0f / s;
        }
        __syncthreads();
        if (tid < 128) {
            int h = tid * 4;
            int j = h >> 6, b = h & 63;
            float4 rv = *(const float4*)(rden_s + b);
            float4 zv;
            zv.x = ev.x * rv.x; zv.y = ev.y * rv.y;
            zv.z = ev.z * rv.z; zv.w = ev.w * rv.w;
            *(float4*)(zo_s + j * 64 + b) = zv;
        }
        __syncthreads();
        // post_mean: one warp per output row
        {
            float s = zo_s[w_id * 64 + lane] + zo_s[w_id * 64 + 32 + lane];
#pragma unroll
            for (int m = 16; m > 0; m >>= 1)
                s += __shfl_xor_sync(0xffffffffu, s, m);
            if (lane == 0) pm_s[w_id] = s * (1.0f / BATCH);
        }
        // emit z_out_stack[t]
        if (tid < 64) {
            int b = ic * 8 + (tid >> 3), j = tid & 7;
            out[(size_t)t * (BATCH * NOUT) + b * NOUT + oc * 8 + j] =
                zo_s[j * 64 + b];
        }

        // GEMM2: pp[j][i] = sum_b zo[j][b] * psp[b][i]
        unsigned long long acc2[8];
#pragma unroll
        for (int i = 0; i < 8; i++) acc2[i] = 0ull;
#pragma unroll
        for (int m = 0; m < 8; m++) {
            int b = ksC + (m << 3);
            ulonglong2 pv = *(const ulonglong2*)(P + b * 68 + (ibC << 2));
#pragma unroll
            for (int jj = 0; jj < 4; jj++) {
                float z = zo_s[(jbC * 4 + jj) * 64 + b];
                unsigned long long zz = pack2(z, z);
                acc2[jj * 2 + 0] = ffma2(zz, pv.x, acc2[jj * 2 + 0]);
                acc2[jj * 2 + 1] = ffma2(zz, pv.y, acc2[jj * 2 + 1]);
            }
        }
#pragma unroll
        for (int i = 0; i < 4; i++) {
            bool hi = ksC & 1;
            unsigned long long send = hi ? acc2[i] : acc2[i + 4];
            unsigned long long keep = hi ? acc2[i + 4] : acc2[i];
            acc2[i] = addf2(keep, __shfl_xor_sync(0xffffffffu, send, 1));
        }
#pragma unroll
        for (int i = 0; i < 2; i++) {
            bool hi = ksC & 2;
            unsigned long long send = hi ? acc2[i] : acc2[i + 2];
            unsigned long long keep = hi ? acc2[i + 2] : acc2[i];
            acc2[i] = addf2(keep, __shfl_xor_sync(0xffffffffu, send, 2));
        }
        {
            bool hi = ksC & 4;
            unsigned long long send = hi ? acc2[0] : acc2[1];
            unsigned long long keep = hi ? acc2[1] : acc2[0];
            acc2[0] = addf2(keep, __shfl_xor_sync(0xffffffffu, send, 4));
        }
        __syncthreads();   // pm_s ready; GEMM2 psp reads complete

        // W/EW update: every thread owns 2 consecutive W elements
        {
            int basev = ((ksC & 1) ? 4 : 0) | ((ksC & 2) ? 2 : 0) | ((ksC & 4) ? 1 : 0);
            int jj = basev >> 1, ip = basev & 1;
            int o_l = jbC * 4 + jj;
            int i_l = (ibC << 2) + 2 * ip;
            float2 ppv;
            unpack2(acc2[0], ppv.x, ppv.y);
            float2* wp  = (float2*)(Wp_s + o_l * 76 + i_l);
            float2* ewp = (float2*)(EWp_s + o_l * 76 + i_l);
            float2 w  = *wp;
            float2 ew = *ewp;
            float pmv = pm_s[o_l];
            float d0 = LRATE * (ew.x * (ppv.x * (1.0f / BATCH)) - pmv);
            float d1 = LRATE * (ew.y * (ppv.y * (1.0f / BATCH)) - pmv);
            w.x += d0; w.y += d1;
            ew.x *= (1.0f - d0 + 0.5f * d0 * d0);
            ew.y *= (1.0f - d1 + 0.5f * d1 * d1);
            *wp = w;
            *ewp = ew;
        }
        if (tid < 8) {
            float bb = bias_s[tid];
            bias_s[tid] = bb + LRATE * (__expf(-bb) - 1.0f) * pm_s[tid];
        }
        __syncthreads();   // W stable before next phase A
    };

    // ================= pipelined main loop ================================
    phaseA(0);
    syncA(0);
    phaseB(0);
    arriveB(0);
    for (int t = 0; t < T_STEPS; ++t) {
        spinB(t);
        phaseC(t);
        if (t + 1 < T_STEPS) {
            phaseA(t + 1);
            syncA(t + 1);
            phaseB(t + 1);
            arriveB(t + 1);
        }
    }

    // ---------------- final membrane potential u_final --------------------
    if (write_u && tid < 64) {
        int b = ic * 8 + (tid >> 3);
        int o = oc * 8 + (tid & 7);
        out[(size_t)T_STEPS * BATCH * NOUT + b * NOUT + o] = u_sm[tid];
    }
}

extern "C" void kernel_launch(void* const* d_in, const int* in_sizes, int n_in,
                              void* d_out, int out_size) {
    const float* spikes = nullptr;
    const float* weight = nullptr;
    const float* bias   = nullptr;
    for (int i = 0; i < n_in; i++) {
        if (in_sizes[i] == T_STEPS * BATCH * NIN)      spikes = (const float*)d_in[i];
        else if (in_sizes[i] == NOUT * NIN)            weight = (const float*)d_in[i];
        else if (in_sizes[i] == NOUT)                  bias   = (const float*)d_in[i];
    }
    int write_u = (out_size >= T_STEPS * BATCH * NOUT + BATCH * NOUT) ? 1 : 0;
    bstdp_kernel<<<NCTA, NTHR>>>(spikes, weight, bias, (float*)d_out, write_u);
}